// round 6
// baseline (speedup 1.0000x reference)
#include <cuda_runtime.h>
#include <cuda_fp16.h>

// HashEmbedding: out[t, d] = sum_{h=0..3} weight_table[x[t,h] + 513*h] * emb_table[x[t,h]>>1][d]
// x is int32.
// R6: (a) full emb table cached in smem as fp16 (128 KB) -> no column chunking,
//     gather crossbar bytes halved; f32 weights, f32 accumulation.
//     (b) stores via smem staging + cp.async.bulk 1D (UBLKCP) instead of STG.128
//     (12 cyc/instr LSU cost eliminated). Warp-per-token; 32-token tiles are
//     contiguous 32 KB in gmem -> no tensormap. Double-buffered stages.

#define NUM_HASHES 4
#define D 256
#define W_TABLE 2052           // 512*4 + 4
#define EMB_ROWS 256
#define BLOCK_THREADS 1024
#define T_TILE 32              // tokens per tile (= warps per block)
#define STAGE_BYTES (T_TILE * D * 4)        // 32 KB per buffer

// smem byte offsets
#define OFF_W     0
#define OFF_EMB   ((W_TABLE * 4 + 15) & ~15)                 // 8208
#define OFF_STAGE (((OFF_EMB + EMB_ROWS * D * 2) + 1023) & ~1023)
#define SMEM_BYTES (OFF_STAGE + 2 * STAGE_BYTES)

__global__ __launch_bounds__(BLOCK_THREADS, 1)
void hash_embedding_kernel(const int* __restrict__ x,
                           const float* __restrict__ weight_table,
                           const float* __restrict__ emb_table,
                           float* __restrict__ out,
                           int ntok)
{
    extern __shared__ char smem[];
    float*  s_w   = reinterpret_cast<float*>(smem + OFF_W);
    char*   s_emb = smem + OFF_EMB;          // [256 rows][256 halves] = 512 B/row

    const int tid = threadIdx.x;

    // ---- prologue: stage weight table (f32) ----
    for (int i = tid; i < W_TABLE; i += BLOCK_THREADS) s_w[i] = weight_table[i];

    // ---- prologue: stage emb table converted to fp16 ----
    // 256*256/4 = 16384 float4 groups; 16 per thread.
    for (int i = tid; i < EMB_ROWS * D / 4; i += BLOCK_THREADS) {
        const int r  = i >> 6;          // row
        const int c4 = i & 63;          // float4 group within row
        const float4 v = *reinterpret_cast<const float4*>(emb_table + r * D + c4 * 4);
        __half2 h0 = __floats2half2_rn(v.x, v.y);
        __half2 h1 = __floats2half2_rn(v.z, v.w);
        uint2 packed;
        packed.x = *reinterpret_cast<unsigned int*>(&h0);
        packed.y = *reinterpret_cast<unsigned int*>(&h1);
        *reinterpret_cast<uint2*>(s_emb + r * 512 + c4 * 8) = packed;
    }
    __syncthreads();

    const int wid  = tid >> 5;          // warp = token slot within tile: 0..31
    const int lane = tid & 31;

    const int ntiles = ntok / T_TILE;   // 2048 for 65536
    const int stride = gridDim.x;

    unsigned int it = 0;
    int tile = blockIdx.x;

    // prologue index load for first tile
    int4 xi = (tile < ntiles)
        ? *reinterpret_cast<const int4*>(x + (long long)(tile * T_TILE + wid) * NUM_HASHES)
        : make_int4(0, 0, 0, 0);

    #pragma unroll 1
    for (; tile < ntiles; tile += stride, ++it) {
        char* stage = smem + OFF_STAGE + (it & 1) * STAGE_BYTES;

        // prefetch next tile's indices
        const int tile_next = (tile + stride < ntiles) ? (tile + stride) : tile;
        const int4 xi_next = *reinterpret_cast<const int4*>(
            x + (long long)(tile_next * T_TILE + wid) * NUM_HASHES);

        // weights (broadcast LDS)
        const float w0 = s_w[xi.x];
        const float w1 = s_w[xi.y + 513];
        const float w2 = s_w[xi.z + 1026];
        const float w3 = s_w[xi.w + 1539];

        // fp16 row bases (idx = x >> 1; row = 512 B)
        const char* r0 = s_emb + ((xi.x >> 1) << 9);
        const char* r1 = s_emb + ((xi.y >> 1) << 9);
        const char* r2 = s_emb + ((xi.z >> 1) << 9);
        const char* r3 = s_emb + ((xi.w >> 1) << 9);

        // Part A: cols [lane*4, lane*4+4)   -> row byte offset lane*8
        // Part B: cols [128+lane*4, ...)    -> row byte offset 256 + lane*8
        float a0 = 0.f, a1 = 0.f, a2 = 0.f, a3 = 0.f;
        float b0 = 0.f, b1 = 0.f, b2 = 0.f, b3 = 0.f;

        const int offA = lane * 8;
        const int offB = 256 + lane * 8;

        #define ACC(rp, w)                                                        \
        {                                                                         \
            uint2 ga = *reinterpret_cast<const uint2*>((rp) + offA);              \
            uint2 gb = *reinterpret_cast<const uint2*>((rp) + offB);              \
            float2 fa0 = __half22float2(*reinterpret_cast<__half2*>(&ga.x));      \
            float2 fa1 = __half22float2(*reinterpret_cast<__half2*>(&ga.y));      \
            float2 fb0 = __half22float2(*reinterpret_cast<__half2*>(&gb.x));      \
            float2 fb1 = __half22float2(*reinterpret_cast<__half2*>(&gb.y));      \
            a0 += (w) * fa0.x;  a1 += (w) * fa0.y;                                \
            a2 += (w) * fa1.x;  a3 += (w) * fa1.y;                                \
            b0 += (w) * fb0.x;  b1 += (w) * fb0.y;                                \
            b2 += (w) * fb1.x;  b3 += (w) * fb1.y;                                \
        }
        ACC(r0, w0)
        ACC(r1, w1)
        ACC(r2, w2)
        ACC(r3, w3)
        #undef ACC

        // stage (token-major, exact gmem layout): token slot = wid, 1024 B/row
        float4 va = make_float4(a0, a1, a2, a3);
        float4 vb = make_float4(b0, b1, b2, b3);
        *reinterpret_cast<float4*>(stage + wid * 1024 + lane * 16)       = va;
        *reinterpret_cast<float4*>(stage + wid * 1024 + 512 + lane * 16) = vb;

        __syncthreads();   // all STS for this buffer done

        if (tid == 0) {
            asm volatile("fence.proxy.async.shared::cta;" ::: "memory");
            unsigned int saddr;
            asm("{ .reg .u64 t; cvta.to.shared.u64 t, %1; cvt.u32.u64 %0, t; }"
                : "=r"(saddr) : "l"(stage));
            const float* gdst = out + (long long)tile * T_TILE * D;
            asm volatile(
                "cp.async.bulk.global.shared::cta.bulk_group [%0], [%1], %2;"
                :: "l"(gdst), "r"(saddr), "r"((unsigned int)STAGE_BYTES)
                : "memory");
            asm volatile("cp.async.bulk.commit_group;" ::: "memory");
            // allow 1 group in flight: the OTHER buffer's copy must be done
            asm volatile("cp.async.bulk.wait_group.read 1;" ::: "memory");
        }
        __syncthreads();   // everyone knows buffer (it+1)&1 is reusable

        xi = xi_next;
    }

    // drain outstanding bulk stores before exit
    if (tid == 0) {
        asm volatile("cp.async.bulk.wait_group 0;" ::: "memory");
    }
}

extern "C" void kernel_launch(void* const* d_in, const int* in_sizes, int n_in,
                              void* d_out, int out_size)
{
    const int*   x            = (const int*)d_in[0];
    const float* weight_table = (const float*)d_in[1];
    const float* emb_table    = (const float*)d_in[2];
    float*       out          = (float*)d_out;

    const int ntok = in_sizes[0] / NUM_HASHES;   // 65536

    cudaFuncSetAttribute(hash_embedding_kernel,
                         cudaFuncAttributeMaxDynamicSharedMemorySize, SMEM_BYTES);

    hash_embedding_kernel<<<148, BLOCK_THREADS, SMEM_BYTES>>>(
        x, weight_table, emb_table, out, ntok);
}

// round 7
// speedup vs baseline: 1.1087x; 1.1087x over previous
#include <cuda_runtime.h>
#include <cuda_fp16.h>

// HashEmbedding: out[t, d] = sum_{h=0..3} weight_table[x[t,h] + 513*h] * emb_table[x[t,h]>>1][d]
// x is int32.
// R7: fp16 full emb table in smem (128 KB, no column chunking) + plain STG.128
// stores, warp-per-token, warp-stride loop. ZERO post-prologue synchronization:
// R6 showed the block-wide TMA staging barriers ate the traffic win.
// 1024-thread blocks, 1 CTA/SM, grid 148.

#define NUM_HASHES 4
#define D 256
#define W_TABLE 2052           // 512*4 + 4
#define EMB_ROWS 256
#define BLOCK_THREADS 1024
#define WARPS_PER_BLOCK (BLOCK_THREADS / 32)
#define GRID_X 148

// smem byte offsets
#define OFF_W     0
#define OFF_EMB   ((W_TABLE * 4 + 15) & ~15)                 // 8208
#define SMEM_BYTES (OFF_EMB + EMB_ROWS * D * 2)              // + 128 KB

__global__ __launch_bounds__(BLOCK_THREADS, 1)
void hash_embedding_kernel(const int* __restrict__ x,
                           const float* __restrict__ weight_table,
                           const float* __restrict__ emb_table,
                           float* __restrict__ out,
                           int ntok)
{
    extern __shared__ char smem[];
    float* s_w   = reinterpret_cast<float*>(smem + OFF_W);
    char*  s_emb = smem + OFF_EMB;          // [256 rows][256 halves] = 512 B/row

    const int tid = threadIdx.x;

    // ---- prologue: stage weight table (f32) ----
    for (int i = tid; i < W_TABLE; i += BLOCK_THREADS) s_w[i] = weight_table[i];

    // ---- prologue: stage emb table converted to fp16 ----
    for (int i = tid; i < EMB_ROWS * D / 4; i += BLOCK_THREADS) {
        const int r  = i >> 6;          // row
        const int c4 = i & 63;          // float4 group within row
        const float4 v = *reinterpret_cast<const float4*>(emb_table + r * D + c4 * 4);
        __half2 h0 = __floats2half2_rn(v.x, v.y);
        __half2 h1 = __floats2half2_rn(v.z, v.w);
        uint2 packed;
        packed.x = *reinterpret_cast<unsigned int*>(&h0);
        packed.y = *reinterpret_cast<unsigned int*>(&h1);
        *reinterpret_cast<uint2*>(s_emb + r * 512 + c4 * 8) = packed;
    }
    __syncthreads();   // the ONLY block-wide sync in the kernel

    const int lane = tid & 31;
    const int gw   = blockIdx.x * WARPS_PER_BLOCK + (tid >> 5);  // global warp id
    const int nw   = GRID_X * WARPS_PER_BLOCK;                   // 4736 warps

    const int offA = lane * 8;          // row bytes for cols [lane*4 .. lane*4+3]
    const int offB = 256 + lane * 8;    // row bytes for cols [128+lane*4 ..]

    int t = gw;
    if (t >= ntok) return;

    // prologue index load (whole warp loads same int4 -> broadcast)
    int4 xi = *reinterpret_cast<const int4*>(x + (long long)t * NUM_HASHES);

    #pragma unroll 1
    for (; t < ntok; t += nw) {
        // prefetch next token's indices
        const int tn = (t + nw < ntok) ? (t + nw) : t;
        const int4 xi_next = *reinterpret_cast<const int4*>(x + (long long)tn * NUM_HASHES);

        // per-sample weights (broadcast LDS)
        const float w0 = s_w[xi.x];
        const float w1 = s_w[xi.y + 513];
        const float w2 = s_w[xi.z + 1026];
        const float w3 = s_w[xi.w + 1539];

        // fp16 row bases (idx = x >> 1; 512 B per row)
        const char* r0 = s_emb + ((xi.x >> 1) << 9);
        const char* r1 = s_emb + ((xi.y >> 1) << 9);
        const char* r2 = s_emb + ((xi.z >> 1) << 9);
        const char* r3 = s_emb + ((xi.w >> 1) << 9);

        float a0 = 0.f, a1 = 0.f, a2 = 0.f, a3 = 0.f;
        float b0 = 0.f, b1 = 0.f, b2 = 0.f, b3 = 0.f;

        #define ACC(rp, w)                                                        \
        {                                                                         \
            uint2 ga = *reinterpret_cast<const uint2*>((rp) + offA);              \
            uint2 gb = *reinterpret_cast<const uint2*>((rp) + offB);              \
            float2 fa0 = __half22float2(*reinterpret_cast<__half2*>(&ga.x));      \
            float2 fa1 = __half22float2(*reinterpret_cast<__half2*>(&ga.y));      \
            float2 fb0 = __half22float2(*reinterpret_cast<__half2*>(&gb.x));      \
            float2 fb1 = __half22float2(*reinterpret_cast<__half2*>(&gb.y));      \
            a0 += (w) * fa0.x;  a1 += (w) * fa0.y;                                \
            a2 += (w) * fa1.x;  a3 += (w) * fa1.y;                                \
            b0 += (w) * fb0.x;  b1 += (w) * fb0.y;                                \
            b2 += (w) * fb1.x;  b3 += (w) * fb1.y;                                \
        }
        ACC(r0, w0)
        ACC(r1, w1)
        ACC(r2, w2)
        ACC(r3, w3)
        #undef ACC

        float* op = out + (long long)t * D + lane * 4;
        *reinterpret_cast<float4*>(op)       = make_float4(a0, a1, a2, a3);
        *reinterpret_cast<float4*>(op + 128) = make_float4(b0, b1, b2, b3);

        xi = xi_next;
    }
}

extern "C" void kernel_launch(void* const* d_in, const int* in_sizes, int n_in,
                              void* d_out, int out_size)
{
    const int*   x            = (const int*)d_in[0];
    const float* weight_table = (const float*)d_in[1];
    const float* emb_table    = (const float*)d_in[2];
    float*       out          = (float*)d_out;

    const int ntok = in_sizes[0] / NUM_HASHES;   // 65536

    cudaFuncSetAttribute(hash_embedding_kernel,
                         cudaFuncAttributeMaxDynamicSharedMemorySize, SMEM_BYTES);

    hash_embedding_kernel<<<GRID_X, BLOCK_THREADS, SMEM_BYTES>>>(
        x, weight_table, emb_table, out, ntok);
}

// round 8
// speedup vs baseline: 1.1218x; 1.0118x over previous
#include <cuda_runtime.h>
#include <cuda_fp16.h>

// HashEmbedding: out[t, d] = sum_{h=0..3} weight_table[x[t,h] + 513*h] * emb_table[x[t,h]>>1][d]
// x is int32.
// R8: R7 (fp16 full table in smem, sync-free warp-per-token) + 2-token ILP per
// warp iteration: 16 gather LDS in flight instead of 8, halved loop overhead.
// 1024-thread blocks, 1 CTA/SM, grid 148.

#define NUM_HASHES 4
#define D 256
#define W_TABLE 2052           // 512*4 + 4
#define EMB_ROWS 256
#define BLOCK_THREADS 1024
#define WARPS_PER_BLOCK (BLOCK_THREADS / 32)
#define GRID_X 148

// smem byte offsets
#define OFF_W     0
#define OFF_EMB   ((W_TABLE * 4 + 15) & ~15)                 // 8208
#define SMEM_BYTES (OFF_EMB + EMB_ROWS * D * 2)              // + 128 KB

__global__ __launch_bounds__(BLOCK_THREADS, 1)
void hash_embedding_kernel(const int* __restrict__ x,
                           const float* __restrict__ weight_table,
                           const float* __restrict__ emb_table,
                           float* __restrict__ out,
                           int ntok)
{
    extern __shared__ char smem[];
    float* s_w   = reinterpret_cast<float*>(smem + OFF_W);
    char*  s_emb = smem + OFF_EMB;          // [256 rows][256 halves] = 512 B/row

    const int tid = threadIdx.x;

    // ---- prologue: stage weight table (f32) ----
    for (int i = tid; i < W_TABLE; i += BLOCK_THREADS) s_w[i] = weight_table[i];

    // ---- prologue: stage emb table converted to fp16 ----
    for (int i = tid; i < EMB_ROWS * D / 4; i += BLOCK_THREADS) {
        const int r  = i >> 6;          // row
        const int c4 = i & 63;          // float4 group within row
        const float4 v = *reinterpret_cast<const float4*>(emb_table + r * D + c4 * 4);
        __half2 h0 = __floats2half2_rn(v.x, v.y);
        __half2 h1 = __floats2half2_rn(v.z, v.w);
        uint2 packed;
        packed.x = *reinterpret_cast<unsigned int*>(&h0);
        packed.y = *reinterpret_cast<unsigned int*>(&h1);
        *reinterpret_cast<uint2*>(s_emb + r * 512 + c4 * 8) = packed;
    }
    __syncthreads();   // the ONLY block-wide sync in the kernel

    const int lane = tid & 31;
    const int gw   = blockIdx.x * WARPS_PER_BLOCK + (tid >> 5);  // global warp id
    const int nw   = GRID_X * WARPS_PER_BLOCK;                   // 4736 warps

    const int offA = lane * 8;          // row bytes for cols [lane*4 .. lane*4+3]
    const int offB = 256 + lane * 8;    // row bytes for cols [128+lane*4 ..]

    const int npairs = ntok >> 1;       // 32768; every pair fully valid

    int p = gw;
    if (p >= npairs) return;

    // prologue index loads for the first pair (same 128B line)
    int4 xi0 = *reinterpret_cast<const int4*>(x + (long long)(2 * p)     * NUM_HASHES);
    int4 xi1 = *reinterpret_cast<const int4*>(x + (long long)(2 * p + 1) * NUM_HASHES);

    #pragma unroll 1
    for (; p < npairs; p += nw) {
        // prefetch next pair's indices
        const int pn = (p + nw < npairs) ? (p + nw) : p;
        const int4 xn0 = *reinterpret_cast<const int4*>(x + (long long)(2 * pn)     * NUM_HASHES);
        const int4 xn1 = *reinterpret_cast<const int4*>(x + (long long)(2 * pn + 1) * NUM_HASHES);

        // per-sample weights (broadcast LDS)
        const float u0 = s_w[xi0.x];
        const float u1 = s_w[xi0.y + 513];
        const float u2 = s_w[xi0.z + 1026];
        const float u3 = s_w[xi0.w + 1539];
        const float v0 = s_w[xi1.x];
        const float v1 = s_w[xi1.y + 513];
        const float v2 = s_w[xi1.z + 1026];
        const float v3 = s_w[xi1.w + 1539];

        // fp16 row bases (idx = x >> 1; 512 B per row)
        const char* p00 = s_emb + ((xi0.x >> 1) << 9);
        const char* p01 = s_emb + ((xi0.y >> 1) << 9);
        const char* p02 = s_emb + ((xi0.z >> 1) << 9);
        const char* p03 = s_emb + ((xi0.w >> 1) << 9);
        const char* p10 = s_emb + ((xi1.x >> 1) << 9);
        const char* p11 = s_emb + ((xi1.y >> 1) << 9);
        const char* p12 = s_emb + ((xi1.z >> 1) << 9);
        const char* p13 = s_emb + ((xi1.w >> 1) << 9);

        // Batch all 16 gather loads up front (16 outstanding LDS.64).
        uint2 gA0[4], gB0[4], gA1[4], gB1[4];
        gA0[0] = *reinterpret_cast<const uint2*>(p00 + offA);
        gA0[1] = *reinterpret_cast<const uint2*>(p01 + offA);
        gA0[2] = *reinterpret_cast<const uint2*>(p02 + offA);
        gA0[3] = *reinterpret_cast<const uint2*>(p03 + offA);
        gA1[0] = *reinterpret_cast<const uint2*>(p10 + offA);
        gA1[1] = *reinterpret_cast<const uint2*>(p11 + offA);
        gA1[2] = *reinterpret_cast<const uint2*>(p12 + offA);
        gA1[3] = *reinterpret_cast<const uint2*>(p13 + offA);
        gB0[0] = *reinterpret_cast<const uint2*>(p00 + offB);
        gB0[1] = *reinterpret_cast<const uint2*>(p01 + offB);
        gB0[2] = *reinterpret_cast<const uint2*>(p02 + offB);
        gB0[3] = *reinterpret_cast<const uint2*>(p03 + offB);
        gB1[0] = *reinterpret_cast<const uint2*>(p10 + offB);
        gB1[1] = *reinterpret_cast<const uint2*>(p11 + offB);
        gB1[2] = *reinterpret_cast<const uint2*>(p12 + offB);
        gB1[3] = *reinterpret_cast<const uint2*>(p13 + offB);

        const float wt0[4] = {u0, u1, u2, u3};
        const float wt1[4] = {v0, v1, v2, v3};

        float a0[4] = {0.f, 0.f, 0.f, 0.f};   // token0 half A
        float b0[4] = {0.f, 0.f, 0.f, 0.f};   // token0 half B
        float a1[4] = {0.f, 0.f, 0.f, 0.f};   // token1 half A
        float b1[4] = {0.f, 0.f, 0.f, 0.f};   // token1 half B

        #pragma unroll
        for (int h = 0; h < 4; ++h) {
            float2 f0 = __half22float2(*reinterpret_cast<__half2*>(&gA0[h].x));
            float2 f1 = __half22float2(*reinterpret_cast<__half2*>(&gA0[h].y));
            a0[0] += wt0[h] * f0.x;  a0[1] += wt0[h] * f0.y;
            a0[2] += wt0[h] * f1.x;  a0[3] += wt0[h] * f1.y;

            float2 g0 = __half22float2(*reinterpret_cast<__half2*>(&gB0[h].x));
            float2 g1 = __half22float2(*reinterpret_cast<__half2*>(&gB0[h].y));
            b0[0] += wt0[h] * g0.x;  b0[1] += wt0[h] * g0.y;
            b0[2] += wt0[h] * g1.x;  b0[3] += wt0[h] * g1.y;

            float2 h0 = __half22float2(*reinterpret_cast<__half2*>(&gA1[h].x));
            float2 h1 = __half22float2(*reinterpret_cast<__half2*>(&gA1[h].y));
            a1[0] += wt1[h] * h0.x;  a1[1] += wt1[h] * h0.y;
            a1[2] += wt1[h] * h1.x;  a1[3] += wt1[h] * h1.y;

            float2 k0 = __half22float2(*reinterpret_cast<__half2*>(&gB1[h].x));
            float2 k1 = __half22float2(*reinterpret_cast<__half2*>(&gB1[h].y));
            b1[0] += wt1[h] * k0.x;  b1[1] += wt1[h] * k0.y;
            b1[2] += wt1[h] * k1.x;  b1[3] += wt1[h] * k1.y;
        }

        float* op = out + (long long)(2 * p) * D + lane * 4;
        *reinterpret_cast<float4*>(op)             = make_float4(a0[0], a0[1], a0[2], a0[3]);
        *reinterpret_cast<float4*>(op + 128)       = make_float4(b0[0], b0[1], b0[2], b0[3]);
        *reinterpret_cast<float4*>(op + 256)       = make_float4(a1[0], a1[1], a1[2], a1[3]);
        *reinterpret_cast<float4*>(op + 384)       = make_float4(b1[0], b1[1], b1[2], b1[3]);

        xi0 = xn0;
        xi1 = xn1;
    }
}

extern "C" void kernel_launch(void* const* d_in, const int* in_sizes, int n_in,
                              void* d_out, int out_size)
{
    const int*   x            = (const int*)d_in[0];
    const float* weight_table = (const float*)d_in[1];
    const float* emb_table    = (const float*)d_in[2];
    float*       out          = (float*)d_out;

    const int ntok = in_sizes[0] / NUM_HASHES;   // 65536

    cudaFuncSetAttribute(hash_embedding_kernel,
                         cudaFuncAttributeMaxDynamicSharedMemorySize, SMEM_BYTES);

    hash_embedding_kernel<<<GRID_X, BLOCK_THREADS, SMEM_BYTES>>>(
        x, weight_table, emb_table, out, ntok);
}